// round 4
// baseline (speedup 1.0000x reference)
#include <cuda_runtime.h>
#include <math.h>

#define An 32
#define Bn 128
#define Nn 4096
#define Tt 5
#define Hh 4
#define DHh 64
#define Dd 256
#define Ll 64
#define FIN1 24

typedef unsigned long long ull;

// scratch
__device__ float g_ego[Tt * Bn * Dd];    // [t*128+b][256]
__device__ float g_k[Tt * Bn * Dd];
__device__ float g_v[Tt * Bn * Dd];
__device__ float g_q[Bn * Dd];
__device__ float g_ctx[Bn * Dd];
__device__ float g_feat[Bn * Dd];

// ---- packed f32x2 helpers ----
__device__ __forceinline__ ull pack2(float lo, float hi) {
    ull r; asm("mov.b64 %0, {%1, %2};" : "=l"(r) : "f"(lo), "f"(hi)); return r;
}
__device__ __forceinline__ ull dup2(float v) { return pack2(v, v); }
__device__ __forceinline__ void fma2(ull& acc, ull a, ull b) {
    asm("fma.rn.f32x2 %0, %1, %2, %0;" : "+l"(acc) : "l"(a), "l"(b));
}
__device__ __forceinline__ float2 unpack2(ull v) {
    float2 f; asm("mov.b64 {%0, %1}, %2;" : "=f"(f.x), "=f"(f.y) : "l"(v)); return f;
}

// ---------------------------------------------------------------------------
// Shared GEMM tile body: 32 rows (x_sm, row-major K=256) times W(256x256),
// thread = 8 rows x 2 col-pairs. Writes out[row][256] row-major + bias.
// ---------------------------------------------------------------------------
__device__ __forceinline__ void gemm_tile32(const float* __restrict__ x_sm,
                                            const float* __restrict__ W,
                                            const float* __restrict__ bias,
                                            float* __restrict__ out, bool relu)
{
    const int tid = threadIdx.x;
    const int cp = tid & 63;
    const int r0 = (tid >> 6) * 8;

    ull acc0[8], acc1[8];
    #pragma unroll
    for (int i = 0; i < 8; i++) { acc0[i] = 0ull; acc1[i] = 0ull; }

    #pragma unroll 2
    for (int k = 0; k < Dd; k += 2) {
        float2 xv[8];
        #pragma unroll
        for (int i = 0; i < 8; i++)
            xv[i] = *reinterpret_cast<const float2*>(&x_sm[(r0 + i) * Dd + k]);
        {
            const ull* Wr = reinterpret_cast<const ull*>(W + (size_t)k * Dd);
            ull w0 = __ldg(&Wr[cp]), w1 = __ldg(&Wr[cp + 64]);
            #pragma unroll
            for (int i = 0; i < 8; i++) {
                ull d = dup2(xv[i].x);
                fma2(acc0[i], d, w0); fma2(acc1[i], d, w1);
            }
        }
        {
            const ull* Wr = reinterpret_cast<const ull*>(W + (size_t)(k + 1) * Dd);
            ull w0 = __ldg(&Wr[cp]), w1 = __ldg(&Wr[cp + 64]);
            #pragma unroll
            for (int i = 0; i < 8; i++) {
                ull d = dup2(xv[i].y);
                fma2(acc0[i], d, w0); fma2(acc1[i], d, w1);
            }
        }
    }

    const int c0 = 2 * cp;
    const int c1 = c0 + 128;
    float2 bv0 = *reinterpret_cast<const float2*>(&bias[c0]);
    float2 bv1 = *reinterpret_cast<const float2*>(&bias[c1]);
    #pragma unroll
    for (int i = 0; i < 8; i++) {
        float2 o0 = unpack2(acc0[i]);
        float2 o1 = unpack2(acc1[i]);
        o0.x += bv0.x; o0.y += bv0.y; o1.x += bv1.x; o1.y += bv1.y;
        if (relu) {
            o0.x = fmaxf(o0.x, 0.f); o0.y = fmaxf(o0.y, 0.f);
            o1.x = fmaxf(o1.x, 0.f); o1.y = fmaxf(o1.y, 0.f);
        }
        *reinterpret_cast<float2*>(&out[(r0 + i) * Dd + c0]) = o0;
        *reinterpret_cast<float2*>(&out[(r0 + i) * Dd + c1]) = o1;
    }
}

// smem layout (floats) for gnn kernel
#define REGION_OFF   0
#define H_OFF        6912
#define X2_OFF       15232
#define ALS_OFF      23424
#define ALD_OFF      23552
#define A2_OFF       23680
#define SM_FLOATS    23816
#define HSTRIDE      260

// ---------------------------------------------------------------------------
// Fully fused 2-layer GAT per (t, block). Ego output only.
// ---------------------------------------------------------------------------
__global__ __launch_bounds__(256, 2)
void gnn_fused_kernel(const float* __restrict__ node_feats,
                      const float* __restrict__ W1,
                      const float* __restrict__ a1s, const float* __restrict__ a1d,
                      const float* __restrict__ b1,
                      const float* __restrict__ W2,
                      const float* __restrict__ a2s, const float* __restrict__ a2d,
                      const float* __restrict__ b2)
{
    extern __shared__ float sm[];
    float* x1_sm  = sm + REGION_OFF;
    float* W1_sm  = sm + REGION_OFF + 32 * FIN1;
    float* alpha1 = sm + REGION_OFF;
    float* h_sm   = sm + H_OFF;
    float* x2_sm  = sm + X2_OFF;
    float* als    = sm + ALS_OFF;
    float* ald    = sm + ALD_OFF;
    float* alpha2 = sm + A2_OFF;

    const int tid = threadIdx.x;
    const int t   = blockIdx.x / Bn;
    const int bb  = blockIdx.x % Bn;

    {
        const float* xblk = node_feats + ((size_t)t * Nn + (size_t)bb * An) * FIN1;
        for (int i = tid; i < 32 * FIN1; i += 256) x1_sm[i] = xblk[i];
        const float4* Wsrc = reinterpret_cast<const float4*>(W1);
        float4* Wdst = reinterpret_cast<float4*>(W1_sm);
        #pragma unroll
        for (int i = 0; i < (FIN1 * Dd) / 4; i += 256) Wdst[i + tid] = Wsrc[i + tid];
    }
    __syncthreads();

    const int cp = tid & 63;
    const int r0 = (tid >> 6) * 8;

    // GEMM1
    {
        ull acc0[8], acc1[8];
        #pragma unroll
        for (int i = 0; i < 8; i++) { acc0[i] = 0ull; acc1[i] = 0ull; }
        #pragma unroll
        for (int k = 0; k < FIN1; k += 2) {
            float2 xv[8];
            #pragma unroll
            for (int i = 0; i < 8; i++)
                xv[i] = *reinterpret_cast<const float2*>(&x1_sm[(r0 + i) * FIN1 + k]);
            {
                const ull* Wr = reinterpret_cast<const ull*>(&W1_sm[k * Dd]);
                ull w0 = Wr[cp], w1 = Wr[cp + 64];
                #pragma unroll
                for (int i = 0; i < 8; i++) { ull d = dup2(xv[i].x); fma2(acc0[i], d, w0); fma2(acc1[i], d, w1); }
            }
            {
                const ull* Wr = reinterpret_cast<const ull*>(&W1_sm[(k + 1) * Dd]);
                ull w0 = Wr[cp], w1 = Wr[cp + 64];
                #pragma unroll
                for (int i = 0; i < 8; i++) { ull d = dup2(xv[i].y); fma2(acc0[i], d, w0); fma2(acc1[i], d, w1); }
            }
        }
        ull* h64 = reinterpret_cast<ull*>(h_sm);
        #pragma unroll
        for (int i = 0; i < 8; i++) {
            h64[(r0 + i) * (HSTRIDE / 2) + cp]      = acc0[i];
            h64[(r0 + i) * (HSTRIDE / 2) + cp + 64] = acc1[i];
        }
    }
    __syncthreads();

    // logits1
    if (tid < 128) {
        const int r = tid & 31, head = tid >> 5;
        const float* hrow = &h_sm[r * HSTRIDE + head * DHh];
        const float* as = &a1s[head * DHh];
        const float* ad = &a1d[head * DHh];
        float s1 = 0.f, s2 = 0.f;
        #pragma unroll 8
        for (int j = 0; j < DHh; j++) { float hv = hrow[j]; s1 = fmaf(hv, as[j], s1); s2 = fmaf(hv, ad[j], s2); }
        als[head * 32 + r] = s1;
        ald[head * 32 + r] = s2;
    }
    __syncthreads();

    // softmax1 (all dst)
    if (tid < 128) {
        const int d = tid & 31, head = tid >> 5;
        float* arow = &alpha1[head * (32 * 33) + d * 33];
        const float adv = ald[head * 32 + d];
        float m = -1e30f;
        #pragma unroll
        for (int s = 0; s < 32; s++) {
            float e = als[head * 32 + s] + adv;
            e = (e >= 0.f) ? e : 0.2f * e;
            arow[s] = e; m = fmaxf(m, e);
        }
        float z = 0.f;
        #pragma unroll
        for (int s = 0; s < 32; s++) { float p = expf(arow[s] - m); arow[s] = p; z += p; }
        const float inv = 1.f / (z + 1e-16f);
        #pragma unroll
        for (int s = 0; s < 32; s++) arow[s] *= inv;
    }
    __syncthreads();

    // aggregation1 -> x2
    {
        const int head = tid >> 6;
        const int lane = tid & 63;
        const int cpl  = lane & 15;
        const int d0   = (lane >> 4) * 8;
        const ull* h64 = reinterpret_cast<const ull*>(h_sm);
        const float* arow = &alpha1[head * (32 * 33)];

        ull acc0[8], acc1[8];
        #pragma unroll
        for (int i = 0; i < 8; i++) { acc0[i] = 0ull; acc1[i] = 0ull; }
        #pragma unroll 4
        for (int s = 0; s < 32; s++) {
            ull hv0 = h64[s * (HSTRIDE / 2) + head * 32 + cpl];
            ull hv1 = h64[s * (HSTRIDE / 2) + head * 32 + cpl + 16];
            #pragma unroll
            for (int dd = 0; dd < 8; dd++) {
                ull a = dup2(arow[(d0 + dd) * 33 + s]);
                fma2(acc0[dd], a, hv0); fma2(acc1[dd], a, hv1);
            }
        }
        const int c0 = head * 64 + 2 * cpl;
        const int c1 = c0 + 32;
        float2 bv0 = *reinterpret_cast<const float2*>(&b1[c0]);
        float2 bv1 = *reinterpret_cast<const float2*>(&b1[c1]);
        #pragma unroll
        for (int dd = 0; dd < 8; dd++) {
            float2 o0 = unpack2(acc0[dd]);
            float2 o1 = unpack2(acc1[dd]);
            o0.x = fmaxf(o0.x + bv0.x, 0.f); o0.y = fmaxf(o0.y + bv0.y, 0.f);
            o1.x = fmaxf(o1.x + bv1.x, 0.f); o1.y = fmaxf(o1.y + bv1.y, 0.f);
            *reinterpret_cast<float2*>(&x2_sm[(d0 + dd) * Dd + c0]) = o0;
            *reinterpret_cast<float2*>(&x2_sm[(d0 + dd) * Dd + c1]) = o1;
        }
    }
    __syncthreads();

    // GEMM2 (W2 streamed)
    {
        ull acc0[8], acc1[8];
        #pragma unroll
        for (int i = 0; i < 8; i++) { acc0[i] = 0ull; acc1[i] = 0ull; }
        #pragma unroll 2
        for (int k = 0; k < Dd; k += 2) {
            float2 xv[8];
            #pragma unroll
            for (int i = 0; i < 8; i++)
                xv[i] = *reinterpret_cast<const float2*>(&x2_sm[(r0 + i) * Dd + k]);
            {
                const ull* Wr = reinterpret_cast<const ull*>(W2 + (size_t)k * Dd);
                ull w0 = __ldg(&Wr[cp]), w1 = __ldg(&Wr[cp + 64]);
                #pragma unroll
                for (int i = 0; i < 8; i++) { ull d = dup2(xv[i].x); fma2(acc0[i], d, w0); fma2(acc1[i], d, w1); }
            }
            {
                const ull* Wr = reinterpret_cast<const ull*>(W2 + (size_t)(k + 1) * Dd);
                ull w0 = __ldg(&Wr[cp]), w1 = __ldg(&Wr[cp + 64]);
                #pragma unroll
                for (int i = 0; i < 8; i++) { ull d = dup2(xv[i].y); fma2(acc0[i], d, w0); fma2(acc1[i], d, w1); }
            }
        }
        ull* h64 = reinterpret_cast<ull*>(h_sm);
        #pragma unroll
        for (int i = 0; i < 8; i++) {
            h64[(r0 + i) * (HSTRIDE / 2) + cp]      = acc0[i];
            h64[(r0 + i) * (HSTRIDE / 2) + cp + 64] = acc1[i];
        }
    }
    __syncthreads();

    // logits2
    if (tid < 128) {
        const int r = tid & 31, head = tid >> 5;
        const float* hrow = &h_sm[r * HSTRIDE + head * DHh];
        const float* as = &a2s[head * DHh];
        const float* ad = &a2d[head * DHh];
        float s1 = 0.f, s2 = 0.f;
        #pragma unroll 8
        for (int j = 0; j < DHh; j++) { float hv = hrow[j]; s1 = fmaf(hv, as[j], s1); s2 = fmaf(hv, ad[j], s2); }
        als[head * 32 + r] = s1;
        ald[head * 32 + r] = s2;
    }
    __syncthreads();

    // softmax2: dst 0 only
    if (tid < 4) {
        const float adv = ald[tid * 32];
        float* arow = &alpha2[tid * 33];
        float m = -1e30f;
        #pragma unroll
        for (int s = 0; s < 32; s++) {
            float e = als[tid * 32 + s] + adv;
            e = (e >= 0.f) ? e : 0.2f * e;
            arow[s] = e; m = fmaxf(m, e);
        }
        float z = 0.f;
        #pragma unroll
        for (int s = 0; s < 32; s++) { float p = expf(arow[s] - m); arow[s] = p; z += p; }
        const float inv = 1.f / (z + 1e-16f);
        #pragma unroll
        for (int s = 0; s < 32; s++) arow[s] *= inv;
    }
    __syncthreads();

    // aggregation2 (d=0)
    {
        const int c = tid;
        const int head = c >> 6;
        const float* arow = &alpha2[head * 33];
        float acc = 0.f;
        #pragma unroll 8
        for (int s = 0; s < 32; s++)
            acc = fmaf(arow[s], h_sm[s * HSTRIDE + c], acc);
        acc = fmaxf(acc + b2[c], 0.f);
        g_ego[((size_t)t * Bn + bb) * Dd + c] = acc;
    }
}

// ---------------------------------------------------------------------------
// QKV GEMM: 44 CTAs. 0..19 -> K rows, 20..39 -> V rows, 40..43 -> Q (t=4 rows)
// ---------------------------------------------------------------------------
__global__ __launch_bounds__(256)
void qkv_kernel(const float* __restrict__ wq, const float* __restrict__ bq,
                const float* __restrict__ wk, const float* __restrict__ bk,
                const float* __restrict__ wv, const float* __restrict__ bv)
{
    __shared__ float x_sm[32 * Dd];
    const int id = blockIdx.x;
    const int tid = threadIdx.x;

    const float* W; const float* bias; float* out; int row0;
    if (id < 20)      { W = wk; bias = bk; row0 = id * 32;          out = g_k + (size_t)row0 * Dd; }
    else if (id < 40) { W = wv; bias = bv; row0 = (id - 20) * 32;   out = g_v + (size_t)row0 * Dd; }
    else              { W = wq; bias = bq; row0 = 512 + (id - 40) * 32; out = g_q + (size_t)(row0 - 512) * Dd; }

    const float4* src = reinterpret_cast<const float4*>(g_ego + (size_t)row0 * Dd);
    float4* dst = reinterpret_cast<float4*>(x_sm);
    #pragma unroll
    for (int i = 0; i < (32 * Dd) / 4; i += 256) dst[i + tid] = src[i + tid];
    __syncthreads();

    gemm_tile32(x_sm, W, bias, out, false);
}

// ---------------------------------------------------------------------------
// Attention per block: scores (last q row), softmax over T, ctx -> g_ctx
// ---------------------------------------------------------------------------
__global__ __launch_bounds__(256)
void attn_kernel()
{
    __shared__ float ksm[Tt][Dd];
    __shared__ float vsm[Tt][Dd];
    __shared__ float qsm[Dd];
    __shared__ float attn[Hh][Tt];

    const int b = blockIdx.x;
    const int tid = threadIdx.x;
    const int c = tid;

    #pragma unroll
    for (int t = 0; t < Tt; t++) {
        ksm[t][c] = g_k[((size_t)t * Bn + b) * Dd + c];
        vsm[t][c] = g_v[((size_t)t * Bn + b) * Dd + c];
    }
    qsm[c] = g_q[(size_t)b * Dd + c];
    __syncthreads();

    if (tid < Hh * Tt) {
        const int head = tid / Tt;
        const int t = tid % Tt;
        float s = 0.f;
        #pragma unroll 8
        for (int j = 0; j < DHh; j++)
            s = fmaf(qsm[head * DHh + j], ksm[t][head * DHh + j], s);
        attn[head][t] = s * 0.125f;
    }
    __syncthreads();

    if (tid < Hh) {
        float m = -1e30f;
        #pragma unroll
        for (int t = 0; t < Tt; t++) m = fmaxf(m, attn[tid][t]);
        float z = 0.f;
        #pragma unroll
        for (int t = 0; t < Tt; t++) { float p = expf(attn[tid][t] - m); attn[tid][t] = p; z += p; }
        float inv = 1.f / z;
        #pragma unroll
        for (int t = 0; t < Tt; t++) attn[tid][t] *= inv;
    }
    __syncthreads();

    {
        const int head = c >> 6;
        float a = 0.f;
        #pragma unroll
        for (int t = 0; t < Tt; t++) a = fmaf(attn[head][t], vsm[t][c], a);
        g_ctx[(size_t)b * Dd + c] = a;
    }
}

// ---------------------------------------------------------------------------
// feat = ctx @ wo + bo : 4 CTAs of 32 rows
// ---------------------------------------------------------------------------
__global__ __launch_bounds__(256)
void wo_kernel(const float* __restrict__ wo, const float* __restrict__ bo)
{
    __shared__ float x_sm[32 * Dd];
    const int row0 = blockIdx.x * 32;
    const int tid = threadIdx.x;

    const float4* src = reinterpret_cast<const float4*>(g_ctx + (size_t)row0 * Dd);
    float4* dst = reinterpret_cast<float4*>(x_sm);
    #pragma unroll
    for (int i = 0; i < (32 * Dd) / 4; i += 256) dst[i + tid] = src[i + tid];
    __syncthreads();

    gemm_tile32(x_sm, wo, bo, g_feat + (size_t)row0 * Dd, false);
}

// ---------------------------------------------------------------------------
// Output heads per block, batched 8-wide loads for MLP
// ---------------------------------------------------------------------------
__global__ __launch_bounds__(256)
void heads_kernel(const float* __restrict__ lm_w, const float* __restrict__ lm_b,
                  const float* __restrict__ lv_w, const float* __restrict__ lv_b,
                  const float* __restrict__ ap_w, const float* __restrict__ ap_b,
                  const float* __restrict__ bh_w, const float* __restrict__ bh_b,
                  float* __restrict__ out)
{
    __shared__ float feat[Dd];
    __shared__ float musm[Ll];

    const int b = blockIdx.x;
    const int tid = threadIdx.x;
    feat[tid] = g_feat[(size_t)b * Dd + tid];
    __syncthreads();

    float* ob = out + (size_t)b * 400;

    if (tid < 64) {
        float m = lm_b[tid];
        for (int k = 0; k < Dd; k += 8) {
            float w[8], f[8];
            #pragma unroll
            for (int j = 0; j < 8; j++) w[j] = lm_w[(size_t)(k + j) * Ll + tid];
            #pragma unroll
            for (int j = 0; j < 8; j++) f[j] = feat[k + j];
            #pragma unroll
            for (int j = 0; j < 8; j++) m = fmaf(f[j], w[j], m);
        }
        musm[tid] = m;
        ob[tid] = m;
    } else if (tid < 128) {
        const int cc = tid - 64;
        float m = lv_b[cc];
        for (int k = 0; k < Dd; k += 8) {
            float w[8], f[8];
            #pragma unroll
            for (int j = 0; j < 8; j++) w[j] = lv_w[(size_t)(k + j) * Ll + cc];
            #pragma unroll
            for (int j = 0; j < 8; j++) f[j] = feat[k + j];
            #pragma unroll
            for (int j = 0; j < 8; j++) m = fmaf(f[j], w[j], m);
        }
        ob[64 + cc] = m;
    } else if (tid < 144) {
        const int cc = tid - 128;
        float m = bh_b[cc];
        for (int k = 0; k < Dd; k += 8) {
            float w[8], f[8];
            #pragma unroll
            for (int j = 0; j < 8; j++) w[j] = bh_w[(size_t)(k + j) * 16 + cc];
            #pragma unroll
            for (int j = 0; j < 8; j++) f[j] = feat[k + j];
            #pragma unroll
            for (int j = 0; j < 8; j++) m = fmaf(f[j], w[j], m);
        }
        ob[384 + cc] = m;
    }
    __syncthreads();

    {
        float a = ap_b[tid];
        for (int k = 0; k < Ll; k += 8) {
            float w[8], f[8];
            #pragma unroll
            for (int j = 0; j < 8; j++) w[j] = ap_w[(size_t)(k + j) * Dd + tid];
            #pragma unroll
            for (int j = 0; j < 8; j++) f[j] = musm[k + j];
            #pragma unroll
            for (int j = 0; j < 8; j++) a = fmaf(f[j], w[j], a);
        }
        ob[128 + tid] = a;
    }
}

// ---------------------------------------------------------------------------
extern "C" void kernel_launch(void* const* d_in, const int* in_sizes, int n_in,
                              void* d_out, int out_size)
{
    const float* node_feats = (const float*)d_in[0];
    const float* gat1_w  = (const float*)d_in[2];
    const float* gat1_as = (const float*)d_in[3];
    const float* gat1_ad = (const float*)d_in[4];
    const float* gat1_b  = (const float*)d_in[5];
    const float* gat2_w  = (const float*)d_in[6];
    const float* gat2_as = (const float*)d_in[7];
    const float* gat2_ad = (const float*)d_in[8];
    const float* gat2_b  = (const float*)d_in[9];
    const float* wq = (const float*)d_in[10];
    const float* bq = (const float*)d_in[11];
    const float* wk = (const float*)d_in[12];
    const float* bk = (const float*)d_in[13];
    const float* wv = (const float*)d_in[14];
    const float* bv = (const float*)d_in[15];
    const float* wo = (const float*)d_in[16];
    const float* bo = (const float*)d_in[17];
    const float* lm_w = (const float*)d_in[18];
    const float* lm_b = (const float*)d_in[19];
    const float* lv_w = (const float*)d_in[20];
    const float* lv_b = (const float*)d_in[21];
    const float* ap_w = (const float*)d_in[22];
    const float* ap_b = (const float*)d_in[23];
    const float* bh_w = (const float*)d_in[24];
    const float* bh_b = (const float*)d_in[25];
    float* out = (float*)d_out;

    const size_t smb = (size_t)SM_FLOATS * sizeof(float);
    cudaFuncSetAttribute(gnn_fused_kernel, cudaFuncAttributeMaxDynamicSharedMemorySize, (int)smb);

    gnn_fused_kernel<<<Tt * Bn, 256, smb>>>(node_feats,
                                            gat1_w, gat1_as, gat1_ad, gat1_b,
                                            gat2_w, gat2_as, gat2_ad, gat2_b);
    qkv_kernel<<<44, 256>>>(wq, bq, wk, bk, wv, bv);
    attn_kernel<<<Bn, 256>>>();
    wo_kernel<<<4, 256>>>(wo, bo);
    heads_kernel<<<Bn, 256>>>(lm_w, lm_b, lv_w, lv_b, ap_w, ap_b, bh_w, bh_b, out);
}

// round 5
// speedup vs baseline: 1.3678x; 1.3678x over previous
#include <cuda_runtime.h>
#include <math.h>

#define An 32
#define Bn 128
#define Nn 4096
#define Tt 5
#define Hh 4
#define DHh 64
#define Dd 256
#define Ll 64
#define FIN1 24

typedef unsigned long long ull;

// scratch
__device__ float g_ego[Tt * Bn * Dd];    // [t*128+b][256]
__device__ float g_k[Tt * Bn * Dd];
__device__ float g_v[Tt * Bn * Dd];
__device__ float g_q[Bn * Dd];

// ---- packed f32x2 helpers ----
__device__ __forceinline__ ull pack2(float lo, float hi) {
    ull r; asm("mov.b64 %0, {%1, %2};" : "=l"(r) : "f"(lo), "f"(hi)); return r;
}
__device__ __forceinline__ ull dup2(float v) { return pack2(v, v); }
__device__ __forceinline__ void fma2(ull& acc, ull a, ull b) {
    asm("fma.rn.f32x2 %0, %1, %2, %0;" : "+l"(acc) : "l"(a), "l"(b));
}
__device__ __forceinline__ float2 unpack2(ull v) {
    float2 f; asm("mov.b64 {%0, %1}, %2;" : "=f"(f.x), "=f"(f.y) : "l"(v)); return f;
}

// smem layout (floats) for gnn kernel
#define REGION_OFF   0
#define H_OFF        6912
#define X2_OFF       15232
#define ALS_OFF      23424
#define ALD_OFF      23552
#define A2_OFF       23680
#define SM_FLOATS    23816
#define HSTRIDE      260

// ---------------------------------------------------------------------------
// Fully fused 2-layer GAT per (t, block). Ego output only. (proven ~11us)
// ---------------------------------------------------------------------------
__global__ __launch_bounds__(256, 2)
void gnn_fused_kernel(const float* __restrict__ node_feats,
                      const float* __restrict__ W1,
                      const float* __restrict__ a1s, const float* __restrict__ a1d,
                      const float* __restrict__ b1,
                      const float* __restrict__ W2,
                      const float* __restrict__ a2s, const float* __restrict__ a2d,
                      const float* __restrict__ b2)
{
    extern __shared__ float sm[];
    float* x1_sm  = sm + REGION_OFF;
    float* W1_sm  = sm + REGION_OFF + 32 * FIN1;
    float* alpha1 = sm + REGION_OFF;
    float* h_sm   = sm + H_OFF;
    float* x2_sm  = sm + X2_OFF;
    float* als    = sm + ALS_OFF;
    float* ald    = sm + ALD_OFF;
    float* alpha2 = sm + A2_OFF;

    const int tid = threadIdx.x;
    const int t   = blockIdx.x / Bn;
    const int bb  = blockIdx.x % Bn;

    {
        const float* xblk = node_feats + ((size_t)t * Nn + (size_t)bb * An) * FIN1;
        for (int i = tid; i < 32 * FIN1; i += 256) x1_sm[i] = xblk[i];
        const float4* Wsrc = reinterpret_cast<const float4*>(W1);
        float4* Wdst = reinterpret_cast<float4*>(W1_sm);
        #pragma unroll
        for (int i = 0; i < (FIN1 * Dd) / 4; i += 256) Wdst[i + tid] = Wsrc[i + tid];
    }
    __syncthreads();

    const int cp = tid & 63;
    const int r0 = (tid >> 6) * 8;

    // GEMM1
    {
        ull acc0[8], acc1[8];
        #pragma unroll
        for (int i = 0; i < 8; i++) { acc0[i] = 0ull; acc1[i] = 0ull; }
        #pragma unroll
        for (int k = 0; k < FIN1; k += 2) {
            float2 xv[8];
            #pragma unroll
            for (int i = 0; i < 8; i++)
                xv[i] = *reinterpret_cast<const float2*>(&x1_sm[(r0 + i) * FIN1 + k]);
            {
                const ull* Wr = reinterpret_cast<const ull*>(&W1_sm[k * Dd]);
                ull w0 = Wr[cp], w1 = Wr[cp + 64];
                #pragma unroll
                for (int i = 0; i < 8; i++) { ull d = dup2(xv[i].x); fma2(acc0[i], d, w0); fma2(acc1[i], d, w1); }
            }
            {
                const ull* Wr = reinterpret_cast<const ull*>(&W1_sm[(k + 1) * Dd]);
                ull w0 = Wr[cp], w1 = Wr[cp + 64];
                #pragma unroll
                for (int i = 0; i < 8; i++) { ull d = dup2(xv[i].y); fma2(acc0[i], d, w0); fma2(acc1[i], d, w1); }
            }
        }
        ull* h64 = reinterpret_cast<ull*>(h_sm);
        #pragma unroll
        for (int i = 0; i < 8; i++) {
            h64[(r0 + i) * (HSTRIDE / 2) + cp]      = acc0[i];
            h64[(r0 + i) * (HSTRIDE / 2) + cp + 64] = acc1[i];
        }
    }
    __syncthreads();

    // logits1
    if (tid < 128) {
        const int r = tid & 31, head = tid >> 5;
        const float* hrow = &h_sm[r * HSTRIDE + head * DHh];
        const float* as = &a1s[head * DHh];
        const float* ad = &a1d[head * DHh];
        float s1 = 0.f, s2 = 0.f;
        #pragma unroll 8
        for (int j = 0; j < DHh; j++) { float hv = hrow[j]; s1 = fmaf(hv, as[j], s1); s2 = fmaf(hv, ad[j], s2); }
        als[head * 32 + r] = s1;
        ald[head * 32 + r] = s2;
    }
    __syncthreads();

    // softmax1 (all dst)
    if (tid < 128) {
        const int d = tid & 31, head = tid >> 5;
        float* arow = &alpha1[head * (32 * 33) + d * 33];
        const float adv = ald[head * 32 + d];
        float m = -1e30f;
        #pragma unroll
        for (int s = 0; s < 32; s++) {
            float e = als[head * 32 + s] + adv;
            e = (e >= 0.f) ? e : 0.2f * e;
            arow[s] = e; m = fmaxf(m, e);
        }
        float z = 0.f;
        #pragma unroll
        for (int s = 0; s < 32; s++) { float p = expf(arow[s] - m); arow[s] = p; z += p; }
        const float inv = 1.f / (z + 1e-16f);
        #pragma unroll
        for (int s = 0; s < 32; s++) arow[s] *= inv;
    }
    __syncthreads();

    // aggregation1 -> x2
    {
        const int head = tid >> 6;
        const int lane = tid & 63;
        const int cpl  = lane & 15;
        const int d0   = (lane >> 4) * 8;
        const ull* h64 = reinterpret_cast<const ull*>(h_sm);
        const float* arow = &alpha1[head * (32 * 33)];

        ull acc0[8], acc1[8];
        #pragma unroll
        for (int i = 0; i < 8; i++) { acc0[i] = 0ull; acc1[i] = 0ull; }
        #pragma unroll 4
        for (int s = 0; s < 32; s++) {
            ull hv0 = h64[s * (HSTRIDE / 2) + head * 32 + cpl];
            ull hv1 = h64[s * (HSTRIDE / 2) + head * 32 + cpl + 16];
            #pragma unroll
            for (int dd = 0; dd < 8; dd++) {
                ull a = dup2(arow[(d0 + dd) * 33 + s]);
                fma2(acc0[dd], a, hv0); fma2(acc1[dd], a, hv1);
            }
        }
        const int c0 = head * 64 + 2 * cpl;
        const int c1 = c0 + 32;
        float2 bv0 = *reinterpret_cast<const float2*>(&b1[c0]);
        float2 bv1 = *reinterpret_cast<const float2*>(&b1[c1]);
        #pragma unroll
        for (int dd = 0; dd < 8; dd++) {
            float2 o0 = unpack2(acc0[dd]);
            float2 o1 = unpack2(acc1[dd]);
            o0.x = fmaxf(o0.x + bv0.x, 0.f); o0.y = fmaxf(o0.y + bv0.y, 0.f);
            o1.x = fmaxf(o1.x + bv1.x, 0.f); o1.y = fmaxf(o1.y + bv1.y, 0.f);
            *reinterpret_cast<float2*>(&x2_sm[(d0 + dd) * Dd + c0]) = o0;
            *reinterpret_cast<float2*>(&x2_sm[(d0 + dd) * Dd + c1]) = o1;
        }
    }
    __syncthreads();

    // GEMM2 (W2 streamed; 640 CTAs hide latency here)
    {
        ull acc0[8], acc1[8];
        #pragma unroll
        for (int i = 0; i < 8; i++) { acc0[i] = 0ull; acc1[i] = 0ull; }
        #pragma unroll 2
        for (int k = 0; k < Dd; k += 2) {
            float2 xv[8];
            #pragma unroll
            for (int i = 0; i < 8; i++)
                xv[i] = *reinterpret_cast<const float2*>(&x2_sm[(r0 + i) * Dd + k]);
            {
                const ull* Wr = reinterpret_cast<const ull*>(W2 + (size_t)k * Dd);
                ull w0 = __ldg(&Wr[cp]), w1 = __ldg(&Wr[cp + 64]);
                #pragma unroll
                for (int i = 0; i < 8; i++) { ull d = dup2(xv[i].x); fma2(acc0[i], d, w0); fma2(acc1[i], d, w1); }
            }
            {
                const ull* Wr = reinterpret_cast<const ull*>(W2 + (size_t)(k + 1) * Dd);
                ull w0 = __ldg(&Wr[cp]), w1 = __ldg(&Wr[cp + 64]);
                #pragma unroll
                for (int i = 0; i < 8; i++) { ull d = dup2(xv[i].y); fma2(acc0[i], d, w0); fma2(acc1[i], d, w1); }
            }
        }
        ull* h64 = reinterpret_cast<ull*>(h_sm);
        #pragma unroll
        for (int i = 0; i < 8; i++) {
            h64[(r0 + i) * (HSTRIDE / 2) + cp]      = acc0[i];
            h64[(r0 + i) * (HSTRIDE / 2) + cp + 64] = acc1[i];
        }
    }
    __syncthreads();

    // logits2
    if (tid < 128) {
        const int r = tid & 31, head = tid >> 5;
        const float* hrow = &h_sm[r * HSTRIDE + head * DHh];
        const float* as = &a2s[head * DHh];
        const float* ad = &a2d[head * DHh];
        float s1 = 0.f, s2 = 0.f;
        #pragma unroll 8
        for (int j = 0; j < DHh; j++) { float hv = hrow[j]; s1 = fmaf(hv, as[j], s1); s2 = fmaf(hv, ad[j], s2); }
        als[head * 32 + r] = s1;
        ald[head * 32 + r] = s2;
    }
    __syncthreads();

    // softmax2: dst 0 only
    if (tid < 4) {
        const float adv = ald[tid * 32];
        float* arow = &alpha2[tid * 33];
        float m = -1e30f;
        #pragma unroll
        for (int s = 0; s < 32; s++) {
            float e = als[tid * 32 + s] + adv;
            e = (e >= 0.f) ? e : 0.2f * e;
            arow[s] = e; m = fmaxf(m, e);
        }
        float z = 0.f;
        #pragma unroll
        for (int s = 0; s < 32; s++) { float p = expf(arow[s] - m); arow[s] = p; z += p; }
        const float inv = 1.f / (z + 1e-16f);
        #pragma unroll
        for (int s = 0; s < 32; s++) arow[s] *= inv;
    }
    __syncthreads();

    // aggregation2 (d=0)
    {
        const int c = tid;
        const int head = c >> 6;
        const float* arow = &alpha2[head * 33];
        float acc = 0.f;
        #pragma unroll 8
        for (int s = 0; s < 32; s++)
            acc = fmaf(arow[s], h_sm[s * HSTRIDE + c], acc);
        acc = fmaxf(acc + b2[c], 0.f);
        g_ego[((size_t)t * Bn + bb) * Dd + c] = acc;
    }
}

// ---------------------------------------------------------------------------
// QKV GEMM, smem-staged weights. 176 CTAs: tile=(id>>1) 16 rows, ch=(id&1)
// 128-col half. tiles 0..39 K, 40..79 V, 80..87 Q(t=4).
// ---------------------------------------------------------------------------
__global__ __launch_bounds__(256)
void qkv_kernel(const float* __restrict__ wq, const float* __restrict__ bq,
                const float* __restrict__ wk, const float* __restrict__ bk,
                const float* __restrict__ wv, const float* __restrict__ bv)
{
    __shared__ float x_sm[16 * Dd];          // 16 KB
    __shared__ float w_sm[64 * 128];         // 32 KB chunk

    const int id  = blockIdx.x;
    const int tile = id >> 1;
    const int ch   = id & 1;
    const int tid  = threadIdx.x;

    const float* W; const float* bias; float* outbase; int row0; int xrow0;
    if (tile < 40)      { W = wk; bias = bk; row0 = tile * 16;        outbase = g_k; xrow0 = row0; }
    else if (tile < 80) { W = wv; bias = bv; row0 = (tile - 40) * 16; outbase = g_v; xrow0 = row0; }
    else                { W = wq; bias = bq; row0 = (tile - 80) * 16; outbase = g_q; xrow0 = 512 + row0; }

    // load x tile (16 x 256), coalesced float4
    {
        const float4* s4 = reinterpret_cast<const float4*>(g_ego + (size_t)xrow0 * Dd);
        float4* d4 = reinterpret_cast<float4*>(x_sm);
        #pragma unroll
        for (int i = 0; i < (16 * Dd) / 4; i += 256) d4[i + tid] = s4[i + tid];
    }

    const int cp = tid & 63;          // col pair within 128-col half
    const int r0 = (tid >> 6) * 4;    // 4 rows per thread

    ull acc[4];
    #pragma unroll
    for (int i = 0; i < 4; i++) acc[i] = 0ull;

    #pragma unroll 1
    for (int c4 = 0; c4 < 4; c4++) {
        __syncthreads();    // protect w_sm reuse (also covers x_sm first time)
        // stage W rows [c4*64, +64), cols [ch*128, +128): 2048 float4, 8/thread
        {
            float4* wd = reinterpret_cast<float4*>(w_sm);
            #pragma unroll
            for (int i = tid; i < 2048; i += 256) {
                int r  = i >> 5;          // 32 float4 per row
                int c4i = i & 31;
                wd[i] = *reinterpret_cast<const float4*>(&W[(size_t)(c4 * 64 + r) * Dd + ch * 128 + c4i * 4]);
            }
        }
        __syncthreads();

        const ull* wu = reinterpret_cast<const ull*>(w_sm);   // [64][64 ull]
        #pragma unroll 4
        for (int k = 0; k < 64; k += 2) {
            float2 xv[4];
            #pragma unroll
            for (int r = 0; r < 4; r++)
                xv[r] = *reinterpret_cast<const float2*>(&x_sm[(r0 + r) * Dd + c4 * 64 + k]);
            ull w0 = wu[k * 64 + cp];
            ull w1 = wu[(k + 1) * 64 + cp];
            #pragma unroll
            for (int r = 0; r < 4; r++) { ull d = dup2(xv[r].x); fma2(acc[r], d, w0); }
            #pragma unroll
            for (int r = 0; r < 4; r++) { ull d = dup2(xv[r].y); fma2(acc[r], d, w1); }
        }
    }

    const int c = ch * 128 + 2 * cp;
    float2 bv2 = *reinterpret_cast<const float2*>(&bias[c]);
    #pragma unroll
    for (int r = 0; r < 4; r++) {
        float2 o = unpack2(acc[r]);
        o.x += bv2.x; o.y += bv2.y;
        *reinterpret_cast<float2*>(&outbase[(size_t)(row0 + r0 + r) * Dd + c]) = o;
    }
}

// ---------------------------------------------------------------------------
// attn + wo + output heads, fused. One CTA per b. Weight loads 16-wide batched.
// ---------------------------------------------------------------------------
__global__ __launch_bounds__(256)
void post_kernel(const float* __restrict__ wo, const float* __restrict__ bo,
                 const float* __restrict__ lm_w, const float* __restrict__ lm_b,
                 const float* __restrict__ lv_w, const float* __restrict__ lv_b,
                 const float* __restrict__ ap_w, const float* __restrict__ ap_b,
                 const float* __restrict__ bh_w, const float* __restrict__ bh_b,
                 float* __restrict__ out)
{
    __shared__ float ksm[Tt][Dd];
    __shared__ float vsm[Tt][Dd];
    __shared__ float qsm[Dd];
    __shared__ float attn[Hh][Tt];
    __shared__ float ctx[Dd];
    __shared__ float feat[Dd];
    __shared__ float musm[Ll];

    const int b = blockIdx.x;
    const int tid = threadIdx.x;
    const int c = tid;

    #pragma unroll
    for (int t = 0; t < Tt; t++) {
        ksm[t][c] = g_k[((size_t)t * Bn + b) * Dd + c];
        vsm[t][c] = g_v[((size_t)t * Bn + b) * Dd + c];
    }
    qsm[c] = g_q[(size_t)b * Dd + c];
    __syncthreads();

    if (tid < Hh * Tt) {
        const int head = tid / Tt;
        const int t = tid % Tt;
        float s = 0.f;
        #pragma unroll 8
        for (int j = 0; j < DHh; j++)
            s = fmaf(qsm[head * DHh + j], ksm[t][head * DHh + j], s);
        attn[head][t] = s * 0.125f;
    }
    __syncthreads();

    if (tid < Hh) {
        float m = -1e30f;
        #pragma unroll
        for (int t = 0; t < Tt; t++) m = fmaxf(m, attn[tid][t]);
        float z = 0.f;
        #pragma unroll
        for (int t = 0; t < Tt; t++) { float p = expf(attn[tid][t] - m); attn[tid][t] = p; z += p; }
        float inv = 1.f / z;
        #pragma unroll
        for (int t = 0; t < Tt; t++) attn[tid][t] *= inv;
    }
    __syncthreads();

    {
        const int head = c >> 6;
        float a = 0.f;
        #pragma unroll
        for (int t = 0; t < Tt; t++) a = fmaf(attn[head][t], vsm[t][c], a);
        ctx[c] = a;
    }
    __syncthreads();

    // feat = ctx @ wo + bo, 16-wide batched weight loads (MLP=16)
    {
        float f = bo[c];
        #pragma unroll 1
        for (int k = 0; k < Dd; k += 16) {
            float w[16];
            #pragma unroll
            for (int j = 0; j < 16; j++) w[j] = __ldg(&wo[(size_t)(k + j) * Dd + c]);
            #pragma unroll
            for (int j = 0; j < 16; j++) f = fmaf(ctx[k + j], w[j], f);
        }
        feat[c] = f;
    }
    __syncthreads();

    float* ob = out + (size_t)b * 400;

    if (tid < 64) {
        float m = lm_b[tid];
        #pragma unroll 1
        for (int k = 0; k < Dd; k += 16) {
            float w[16];
            #pragma unroll
            for (int j = 0; j < 16; j++) w[j] = __ldg(&lm_w[(size_t)(k + j) * Ll + tid]);
            #pragma unroll
            for (int j = 0; j < 16; j++) m = fmaf(feat[k + j], w[j], m);
        }
        musm[tid] = m;
        ob[tid] = m;
    } else if (tid < 128) {
        const int cc = tid - 64;
        float m = lv_b[cc];
        #pragma unroll 1
        for (int k = 0; k < Dd; k += 16) {
            float w[16];
            #pragma unroll
            for (int j = 0; j < 16; j++) w[j] = __ldg(&lv_w[(size_t)(k + j) * Ll + cc]);
            #pragma unroll
            for (int j = 0; j < 16; j++) m = fmaf(feat[k + j], w[j], m);
        }
        ob[64 + cc] = m;
    } else if (tid < 144) {
        const int cc = tid - 128;
        float m = bh_b[cc];
        #pragma unroll 1
        for (int k = 0; k < Dd; k += 16) {
            float w[16];
            #pragma unroll
            for (int j = 0; j < 16; j++) w[j] = __ldg(&bh_w[(size_t)(k + j) * 16 + cc]);
            #pragma unroll
            for (int j = 0; j < 16; j++) m = fmaf(feat[k + j], w[j], m);
        }
        ob[384 + cc] = m;
    }
    __syncthreads();

    // act = mu @ ap_w + ap_b
    {
        float a = ap_b[c];
        #pragma unroll 1
        for (int k = 0; k < Ll; k += 16) {
            float w[16];
            #pragma unroll
            for (int j = 0; j < 16; j++) w[j] = __ldg(&ap_w[(size_t)(k + j) * Dd + c]);
            #pragma unroll
            for (int j = 0; j < 16; j++) a = fmaf(musm[k + j], w[j], a);
        }
        ob[128 + c] = a;
    }
}

// ---------------------------------------------------------------------------
extern "C" void kernel_launch(void* const* d_in, const int* in_sizes, int n_in,
                              void* d_out, int out_size)
{
    const float* node_feats = (const float*)d_in[0];
    const float* gat1_w  = (const float*)d_in[2];
    const float* gat1_as = (const float*)d_in[3];
    const float* gat1_ad = (const float*)d_in[4];
    const float* gat1_b  = (const float*)d_in[5];
    const float* gat2_w  = (const float*)d_in[6];
    const float* gat2_as = (const float*)d_in[7];
    const float* gat2_ad = (const float*)d_in[8];
    const float* gat2_b  = (const float*)d_in[9];
    const float* wq = (const float*)d_in[10];
    const float* bq = (const float*)d_in[11];
    const float* wk = (const float*)d_in[12];
    const float* bk = (const float*)d_in[13];
    const float* wv = (const float*)d_in[14];
    const float* bv = (const float*)d_in[15];
    const float* wo = (const float*)d_in[16];
    const float* bo = (const float*)d_in[17];
    const float* lm_w = (const float*)d_in[18];
    const float* lm_b = (const float*)d_in[19];
    const float* lv_w = (const float*)d_in[20];
    const float* lv_b = (const float*)d_in[21];
    const float* ap_w = (const float*)d_in[22];
    const float* ap_b = (const float*)d_in[23];
    const float* bh_w = (const float*)d_in[24];
    const float* bh_b = (const float*)d_in[25];
    float* out = (float*)d_out;

    const size_t smb = (size_t)SM_FLOATS * sizeof(float);
    cudaFuncSetAttribute(gnn_fused_kernel, cudaFuncAttributeMaxDynamicSharedMemorySize, (int)smb);

    gnn_fused_kernel<<<Tt * Bn, 256, smb>>>(node_feats,
                                            gat1_w, gat1_as, gat1_ad, gat1_b,
                                            gat2_w, gat2_as, gat2_ad, gat2_b);
    qkv_kernel<<<176, 256>>>(wq, bq, wk, bk, wv, bv);
    post_kernel<<<Bn, 256>>>(wo, bo, lm_w, lm_b, lv_w, lv_b,
                             ap_w, ap_b, bh_w, bh_b, out);
}